// round 13
// baseline (speedup 1.0000x reference)
#include <cuda_runtime.h>
#include <cuda_fp16.h>
#include <cstdint>

// Problem constants
#define BB 16
#define SS 4096
#define EE 1024
#define HH 512
#define NROWS (BB*SS)          // 65536
#define NSPLIT 8               // H split (BN=64)
#define CSPLIT 32              // s-split for context pass
#define NCHUNK 2
#define CHUNK_ROWS (NROWS/NCHUNK)   // 32768 rows = 8 batches

// GEMM tiling: BM=128 x BN=64, 128 threads (4 warps, warp tile 64x32)
#define BM 128
#define BN 64
#define BK 64                  // fp16 elems = 128B rows (SW128 atom)
#define KITERS (EE/BK)         // 16
#define STAGES 3
#define A_BYTES (BM*BK*2)      // 16384
#define B_BYTES (BN*BK*2)      // 8192
#define STAGE_BYTES (A_BYTES + B_BYTES)  // 24576

// Scratch (__device__ globals; allocation-free rule), 16B+ aligned.
__device__ __align__(128) __half g_encH[(size_t)NROWS*EE];   // fp16 encoder copy
__device__ __align__(128) __half g_WeTh[HH*EE];              // We^T fp16, K-major
__device__ __align__(128) float  g_comb[BB*HH];              // dec_proj + bd + be
__device__ __align__(128) float  g_partial[NSPLIT*NROWS];    // partial scores
__device__ __align__(128) float  g_attn[NROWS];              // softmax weights
__device__ __align__(128) float  g_ctx_part[CSPLIT*BB*EE];   // context partials

__device__ __forceinline__ uint32_t smem_u32(const void* p) {
    uint32_t a;
    asm("{ .reg .u64 t; cvta.to.shared.u64 t, %1; cvt.u32.u64 %0, t; }" : "=r"(a) : "l"(p));
    return a;
}
__device__ __forceinline__ void cp16(uint32_t dst, const void* src) {
    asm volatile("cp.async.cg.shared.global [%0], [%1], 16;" :: "r"(dst), "l"(src) : "memory");
}
__device__ __forceinline__ void ldmatrix_x4(uint32_t r[4], uint32_t addr) {
    asm volatile("ldmatrix.sync.aligned.m8n8.x4.shared.b16 {%0,%1,%2,%3}, [%4];"
                 : "=r"(r[0]), "=r"(r[1]), "=r"(r[2]), "=r"(r[3]) : "r"(addr));
}
__device__ __forceinline__ void mma_f16(float d[4], const uint32_t a[4], const uint32_t b[2]) {
    asm volatile(
        "mma.sync.aligned.m16n8k16.row.col.f32.f16.f16.f32 "
        "{%0,%1,%2,%3}, {%4,%5,%6,%7}, {%8,%9}, {%0,%1,%2,%3};"
        : "+f"(d[0]), "+f"(d[1]), "+f"(d[2]), "+f"(d[3])
        : "r"(a[0]), "r"(a[1]), "r"(a[2]), "r"(a[3]), "r"(b[0]), "r"(b[1]));
}

// ---------------------------------------------------------------------------
// Convert one encoder chunk fp32 -> fp16. 32 floats per thread.
// ---------------------------------------------------------------------------
__global__ __launch_bounds__(256) void convert_enc_kernel(const float4* __restrict__ in,
                                                          size_t elem_off) {
    const size_t i = elem_off/32 + (size_t)blockIdx.x * 256 + threadIdx.x;
    float4 v[8];
    #pragma unroll
    for (int j = 0; j < 8; j++) v[j] = in[i*8 + j];
    #pragma unroll
    for (int j = 0; j < 4; j++) {
        __half2 h0 = __floats2half2_rn(v[2*j].x,   v[2*j].y);
        __half2 h1 = __floats2half2_rn(v[2*j].z,   v[2*j].w);
        __half2 h2 = __floats2half2_rn(v[2*j+1].x, v[2*j+1].y);
        __half2 h3 = __floats2half2_rn(v[2*j+1].z, v[2*j+1].w);
        uint4 o;
        o.x = *reinterpret_cast<uint32_t*>(&h0);
        o.y = *reinterpret_cast<uint32_t*>(&h1);
        o.z = *reinterpret_cast<uint32_t*>(&h2);
        o.w = *reinterpret_cast<uint32_t*>(&h3);
        reinterpret_cast<uint4*>(g_encH)[i*4 + j] = o;
    }
}

// ---------------------------------------------------------------------------
// We [1024,512] -> g_WeTh [512,1024] fp16 (transposed, K-major).
// ---------------------------------------------------------------------------
__global__ __launch_bounds__(256) void convert_we_kernel(const float* __restrict__ We) {
    __shared__ float t[32][33];
    const int bx = blockIdx.x;  // K block (32)
    const int by = blockIdx.y;  // N block (16)
    const int x = threadIdx.x & 31;
    const int y = threadIdx.x >> 5;
    #pragma unroll
    for (int i = 0; i < 32; i += 8)
        t[y + i][x] = We[(bx*32 + y + i)*HH + by*32 + x];
    __syncthreads();
    #pragma unroll
    for (int i = 0; i < 32; i += 8)
        g_WeTh[(by*32 + y + i)*EE + bx*32 + x] = __float2half_rn(t[x][y + i]);
}

// ---------------------------------------------------------------------------
// dec_proj: comb[b,h] = dec[b,:] @ Wd[:,h] + bd[h] + be[h].
// Grid (16, 8): 64 h-lanes x 4 K-quarters; smem combine.
// ---------------------------------------------------------------------------
__global__ __launch_bounds__(256) void dec_proj_kernel(
    const float* __restrict__ dec, const float* __restrict__ Wd,
    const float* __restrict__ be, const float* __restrict__ bd) {
    __shared__ float sd[EE];
    __shared__ float part[4][64];
    const int b = blockIdx.x;
    const int hl = threadIdx.x & 63;
    const int q  = threadIdx.x >> 6;          // 0..3
    const int h  = blockIdx.y * 64 + hl;
    for (int i = threadIdx.x; i < EE; i += 256) sd[i] = dec[b*EE + i];
    __syncthreads();
    const float* wp = Wd + (size_t)(q*256)*HH + h;
    const float* dp = sd + q*256;
    float a0 = 0.f, a1 = 0.f, a2 = 0.f, a3 = 0.f;
    #pragma unroll 4
    for (int k = 0; k < 256; k += 4) {
        a0 += dp[k  ] * wp[(size_t)(k  )*HH];
        a1 += dp[k+1] * wp[(size_t)(k+1)*HH];
        a2 += dp[k+2] * wp[(size_t)(k+2)*HH];
        a3 += dp[k+3] * wp[(size_t)(k+3)*HH];
    }
    part[q][hl] = (a0 + a1) + (a2 + a3);
    __syncthreads();
    if (q == 0)
        g_comb[b*HH + h] = (part[0][hl] + part[1][hl]) + (part[2][hl] + part[3][hl])
                         + bd[h] + be[h];
}

// ---------------------------------------------------------------------------
// fp16 GEMM (mma.m16n8k16) + tanh score epilogue, per row-chunk.
// ---------------------------------------------------------------------------
__global__ __launch_bounds__(128, 3) void gemm_score_f16(const float* __restrict__ Wo,
                                                         int r_base) {
    extern __shared__ char dsmem_raw[];
    __shared__ float red[2][BM];
    __shared__ float sm_comb[BN], sm_wo[BN];

    const int tid = threadIdx.x;
    const int n0  = blockIdx.x * BN;
    const int r0  = r_base + blockIdx.y * BM;
    const int b   = r0 >> 12;

    const uint32_t smem_base = (smem_u32(dsmem_raw) + 127u) & ~127u;

    if (tid < BN) {
        sm_comb[tid] = g_comb[b*HH + n0 + tid];
        sm_wo[tid]   = Wo[n0 + tid];
    }

    const int warp = tid >> 5;
    const int lane = tid & 31;
    const int wm = warp >> 1;       // m-warp: rows wm*64..+63
    const int wn = warp & 1;        // n-warp: cols wn*32..+31
    const int g  = lane >> 2;
    const int tig = lane & 3;

    const __half* gA = g_encH + (size_t)r0 * EE;
    const __half* gB = g_WeTh + (size_t)n0 * EE;

    const int lrow = tid >> 3;          // 0..15
    const int lcb  = (tid & 7) * 16;
    const uint32_t st_sw = (uint32_t)(lrow*128 + lcb) ^ ((lrow & 7) << 4);

    float acc[4][4][4];
    #pragma unroll
    for (int mb = 0; mb < 4; mb++)
        #pragma unroll
        for (int nb = 0; nb < 4; nb++)
            #pragma unroll
            for (int e = 0; e < 4; e++) acc[mb][nb][e] = 0.f;

    uint32_t a_raw[4], a_xor[4];
    #pragma unroll
    for (int mb = 0; mb < 4; mb++) {
        int row = wm*64 + mb*16 + (lane & 15);
        a_raw[mb] = row*128 + ((lane >> 4) * 16);
        a_xor[mb] = (row & 7) << 4;
    }
    uint32_t b_raw[2], b_xor[2];
    #pragma unroll
    for (int p = 0; p < 2; p++) {
        int row = wn*32 + p*16 + ((lane & 16) ? 8 : 0) + (lane & 7);
        b_raw[p] = row*128 + (((lane >> 3) & 1) * 16);
        b_xor[p] = (row & 7) << 4;
    }

    // prologue: fill stages 0,1 (iters 0,1)
    #pragma unroll
    for (int p = 0; p < STAGES-1; p++) {
        uint32_t stA = smem_base + p*STAGE_BYTES;
        uint32_t stB = stA + A_BYTES;
        const int k0 = p * BK;
        #pragma unroll
        for (int u = 0; u < 8; u++)
            cp16(stA + st_sw + u*2048, (const char*)(gA + (size_t)(lrow + u*16)*EE + k0) + lcb);
        #pragma unroll
        for (int u = 0; u < 4; u++)
            cp16(stB + st_sw + u*2048, (const char*)(gB + (size_t)(lrow + u*16)*EE + k0) + lcb);
        asm volatile("cp.async.commit_group;" ::: "memory");
    }

    for (int i = 0; i < KITERS; i++) {
        asm volatile("cp.async.wait_group 1;" ::: "memory");
        __syncthreads();

        const uint32_t stA = smem_base + (i % STAGES)*STAGE_BYTES;
        const uint32_t stB = stA + A_BYTES;

        // ks=0 fragments FIRST (feed tensor pipe before the LSU burst)
        uint32_t afr[2][4][4], bfr[2][4][2];
        #pragma unroll
        for (int mb = 0; mb < 4; mb++)
            ldmatrix_x4(afr[0][mb], stA + (a_raw[mb] ^ a_xor[mb]));
        #pragma unroll
        for (int p = 0; p < 2; p++) {
            uint32_t r[4];
            ldmatrix_x4(r, stB + (b_raw[p] ^ b_xor[p]));
            bfr[0][2*p][0]   = r[0]; bfr[0][2*p][1]   = r[1];
            bfr[0][2*p+1][0] = r[2]; bfr[0][2*p+1][1] = r[3];
        }

        // issue loads for iter i+2 into stage (i+2)%STAGES
        if (i + 2 < KITERS) {
            const int sj = (i + 2) % STAGES;
            uint32_t nA = smem_base + sj*STAGE_BYTES;
            uint32_t nB = nA + A_BYTES;
            const int k0 = (i + 2) * BK;
            #pragma unroll
            for (int u = 0; u < 8; u++)
                cp16(nA + st_sw + u*2048, (const char*)(gA + (size_t)(lrow + u*16)*EE + k0) + lcb);
            #pragma unroll
            for (int u = 0; u < 4; u++)
                cp16(nB + st_sw + u*2048, (const char*)(gB + (size_t)(lrow + u*16)*EE + k0) + lcb);
        }
        asm volatile("cp.async.commit_group;" ::: "memory");

        #pragma unroll
        for (int ks = 0; ks < 4; ks++) {
            const int cur = ks & 1, nxt = cur ^ 1;
            if (ks < 3) {
                #pragma unroll
                for (int mb = 0; mb < 4; mb++)
                    ldmatrix_x4(afr[nxt][mb], stA + ((a_raw[mb] + (ks+1)*32) ^ a_xor[mb]));
                #pragma unroll
                for (int p = 0; p < 2; p++) {
                    uint32_t r[4];
                    ldmatrix_x4(r, stB + ((b_raw[p] + (ks+1)*32) ^ b_xor[p]));
                    bfr[nxt][2*p][0]   = r[0]; bfr[nxt][2*p][1]   = r[1];
                    bfr[nxt][2*p+1][0] = r[2]; bfr[nxt][2*p+1][1] = r[3];
                }
            }
            #pragma unroll
            for (int mb = 0; mb < 4; mb++)
                #pragma unroll
                for (int nb = 0; nb < 4; nb++)
                    mma_f16(acc[mb][nb], afr[cur][mb], bfr[cur][nb]);
        }
    }

    // Epilogue: score = sum_n tanh(acc + comb[n]) * wo[n]  (bo shift-invariant)
    float rs[4][2];
    #pragma unroll
    for (int mb = 0; mb < 4; mb++) { rs[mb][0] = 0.f; rs[mb][1] = 0.f; }
    #pragma unroll
    for (int mb = 0; mb < 4; mb++) {
        #pragma unroll
        for (int nb = 0; nb < 4; nb++) {
            int col = wn*32 + nb*8 + tig*2;
            float c0 = sm_comb[col], c1 = sm_comb[col+1];
            float w0 = sm_wo[col],   w1 = sm_wo[col+1];
            float t0, t1, t2, t3;
            asm("tanh.approx.f32 %0, %1;" : "=f"(t0) : "f"(acc[mb][nb][0] + c0));
            asm("tanh.approx.f32 %0, %1;" : "=f"(t1) : "f"(acc[mb][nb][1] + c1));
            asm("tanh.approx.f32 %0, %1;" : "=f"(t2) : "f"(acc[mb][nb][2] + c0));
            asm("tanh.approx.f32 %0, %1;" : "=f"(t3) : "f"(acc[mb][nb][3] + c1));
            rs[mb][0] += t0*w0 + t1*w1;
            rs[mb][1] += t2*w0 + t3*w1;
        }
    }
    #pragma unroll
    for (int mb = 0; mb < 4; mb++)
        #pragma unroll
        for (int hh = 0; hh < 2; hh++) {
            float v = rs[mb][hh];
            v += __shfl_xor_sync(0xffffffffu, v, 1);
            v += __shfl_xor_sync(0xffffffffu, v, 2);
            if (tig == 0) red[wn][wm*64 + mb*16 + hh*8 + g] = v;
        }
    __syncthreads();
    if (tid < BM)
        g_partial[blockIdx.x * NROWS + r0 + tid] = red[0][tid] + red[1][tid];
}

// ---------------------------------------------------------------------------
// softmax over S per batch (sums 8 N-chunk partials); b = b_base + blockIdx.x
// ---------------------------------------------------------------------------
__global__ __launch_bounds__(1024) void softmax_kernel(int b_base) {
    const int b = b_base + blockIdx.x;
    const int tid = threadIdx.x;
    __shared__ float sred[32];
    __shared__ float sbcast;

    float sc[4];
    float m = -1e30f;
    #pragma unroll
    for (int i = 0; i < 4; i++) {
        int s = b*SS + tid + i*1024;
        float v = 0.f;
        #pragma unroll
        for (int p = 0; p < NSPLIT; p++) v += g_partial[p*NROWS + s];
        sc[i] = v;
        m = fmaxf(m, v);
    }
    #pragma unroll
    for (int o = 16; o; o >>= 1) m = fmaxf(m, __shfl_xor_sync(0xffffffffu, m, o));
    if ((tid & 31) == 0) sred[tid >> 5] = m;
    __syncthreads();
    if (tid < 32) {
        float v = sred[tid];
        #pragma unroll
        for (int o = 16; o; o >>= 1) v = fmaxf(v, __shfl_xor_sync(0xffffffffu, v, o));
        if (tid == 0) sbcast = v;
    }
    __syncthreads();
    const float bm = sbcast;

    float sum = 0.f;
    #pragma unroll
    for (int i = 0; i < 4; i++) { sc[i] = __expf(sc[i] - bm); sum += sc[i]; }
    #pragma unroll
    for (int o = 16; o; o >>= 1) sum += __shfl_xor_sync(0xffffffffu, sum, o);
    __syncthreads();
    if ((tid & 31) == 0) sred[tid >> 5] = sum;
    __syncthreads();
    if (tid < 32) {
        float v = sred[tid];
        #pragma unroll
        for (int o = 16; o; o >>= 1) v += __shfl_xor_sync(0xffffffffu, v, o);
        if (tid == 0) sbcast = v;
    }
    __syncthreads();
    const float inv = 1.0f / sbcast;
    #pragma unroll
    for (int i = 0; i < 4; i++) g_attn[b*SS + tid + i*1024] = sc[i] * inv;
}

// ---------------------------------------------------------------------------
// Context partials from fp16 encoder copy; b = b_base + blockIdx.x.
// ---------------------------------------------------------------------------
__global__ __launch_bounds__(256) void ctx_partial_kernel(int b_base) {
    __shared__ float sa[128];
    __shared__ float part[128][8];
    const int b = b_base + blockIdx.x, sp = blockIdx.y;
    const int tid = threadIdx.x;
    const int half = tid >> 7;
    const int c = tid & 127;
    if (tid < 128) sa[tid] = g_attn[b*SS + sp*128 + tid];
    __syncthreads();

    const __half* ep = g_encH + ((size_t)(b*SS + sp*128 + half)) * EE + c*8;
    float a[8] = {0,0,0,0,0,0,0,0};
    #pragma unroll 8
    for (int s = 0; s < 128; s += 2) {
        uint4 v = *reinterpret_cast<const uint4*>(ep + (size_t)s*EE);
        float w = sa[s + half];
        __half2 h0 = *reinterpret_cast<__half2*>(&v.x);
        __half2 h1 = *reinterpret_cast<__half2*>(&v.y);
        __half2 h2 = *reinterpret_cast<__half2*>(&v.z);
        __half2 h3 = *reinterpret_cast<__half2*>(&v.w);
        float2 f0 = __half22float2(h0), f1 = __half22float2(h1);
        float2 f2 = __half22float2(h2), f3 = __half22float2(h3);
        a[0] += w*f0.x; a[1] += w*f0.y; a[2] += w*f1.x; a[3] += w*f1.y;
        a[4] += w*f2.x; a[5] += w*f2.y; a[6] += w*f3.x; a[7] += w*f3.y;
    }
    if (half == 1) {
        #pragma unroll
        for (int j = 0; j < 8; j++) part[c][j] = a[j];
    }
    __syncthreads();
    if (half == 0) {
        float4 o0, o1;
        o0.x = a[0] + part[c][0]; o0.y = a[1] + part[c][1];
        o0.z = a[2] + part[c][2]; o0.w = a[3] + part[c][3];
        o1.x = a[4] + part[c][4]; o1.y = a[5] + part[c][5];
        o1.z = a[6] + part[c][6]; o1.w = a[7] + part[c][7];
        float* dst = &g_ctx_part[(size_t)(sp*BB + b)*EE + c*8];
        *reinterpret_cast<float4*>(dst)     = o0;
        *reinterpret_cast<float4*>(dst + 4) = o1;
    }
}

// ---------------------------------------------------------------------------
// Final reduce of context partials.
// ---------------------------------------------------------------------------
__global__ __launch_bounds__(256) void ctx_reduce_kernel(float* __restrict__ out) {
    const int i = blockIdx.x * 256 + threadIdx.x;  // 16384 outputs
    float acc = 0.f;
    #pragma unroll
    for (int s = 0; s < CSPLIT; s++) acc += g_ctx_part[(size_t)s*BB*EE + i];
    out[i] = acc;
}

// ---------------------------------------------------------------------------
extern "C" void kernel_launch(void* const* d_in, const int* in_sizes, int n_in,
                              void* d_out, int out_size) {
    const float* enc = (const float*)d_in[0];  // [16,4096,1024]
    const float* dec = (const float*)d_in[1];  // [16,1024]
    const float* We  = (const float*)d_in[2];  // [1024,512]
    const float* be  = (const float*)d_in[3];  // [512]
    const float* Wd  = (const float*)d_in[4];  // [1024,512]
    const float* bd  = (const float*)d_in[5];  // [512]
    const float* Wo  = (const float*)d_in[6];  // [512,1]
    // d_in[7] = bo: softmax shift-invariant -> unused.

    // One-time stream/event resources (init only; captured graph identical
    // on every capture).
    static cudaStream_t s2 = nullptr;
    static cudaEvent_t ev_fork = nullptr, ev_w = nullptr, ev_c0 = nullptr,
                       ev_c1 = nullptr, ev_g0 = nullptr, ev_t2 = nullptr;
    if (s2 == nullptr) {
        cudaStreamCreateWithFlags(&s2, cudaStreamNonBlocking);
        cudaEventCreateWithFlags(&ev_fork, cudaEventDisableTiming);
        cudaEventCreateWithFlags(&ev_w,  cudaEventDisableTiming);
        cudaEventCreateWithFlags(&ev_c0, cudaEventDisableTiming);
        cudaEventCreateWithFlags(&ev_c1, cudaEventDisableTiming);
        cudaEventCreateWithFlags(&ev_g0, cudaEventDisableTiming);
        cudaEventCreateWithFlags(&ev_t2, cudaEventDisableTiming);
    }

    const int dyn_smem = STAGES*STAGE_BYTES + 256;  // 73984
    cudaFuncSetAttribute(gemm_score_f16,
                         cudaFuncAttributeMaxDynamicSharedMemorySize, dyn_smem);

    const int conv_blocks = (CHUNK_ROWS * (EE/32)) / 256;   // 4096
    const int HALF_B = BB / NCHUNK;                          // 8 batches

    // s2: weight-side kernels first.
    cudaEventRecord(ev_fork, 0);
    cudaStreamWaitEvent(s2, ev_fork, 0);
    convert_we_kernel<<<dim3(EE/32, HH/32), 256, 0, s2>>>(We);
    dec_proj_kernel<<<dim3(BB, HH/64), 256, 0, s2>>>(dec, Wd, be, bd);
    cudaEventRecord(ev_w, s2);

    // main: convert chunk 0.
    convert_enc_kernel<<<conv_blocks, 256>>>((const float4*)enc, 0);
    cudaEventRecord(ev_c0, 0);

    // s2: convert chunk 1 (starts after conv0 -> overlaps gemm0).
    cudaStreamWaitEvent(s2, ev_c0, 0);
    convert_enc_kernel<<<conv_blocks, 256, 0, s2>>>(
        (const float4*)enc, (size_t)CHUNK_ROWS * EE);
    cudaEventRecord(ev_c1, s2);

    // main: gemm chunk 0 (needs weights + conv0).
    cudaStreamWaitEvent(0, ev_w, 0);
    gemm_score_f16<<<dim3(NSPLIT, CHUNK_ROWS/BM), 128, dyn_smem>>>(Wo, 0);
    cudaEventRecord(ev_g0, 0);

    // s2: softmax + ctx for batches 0-7 (overlaps gemm1 on main).
    cudaStreamWaitEvent(s2, ev_g0, 0);
    softmax_kernel<<<HALF_B, 1024, 0, s2>>>(0);
    ctx_partial_kernel<<<dim3(HALF_B, CSPLIT), 256, 0, s2>>>(0);
    cudaEventRecord(ev_t2, s2);

    // main: gemm chunk 1 (needs conv1), then tail for batches 8-15.
    cudaStreamWaitEvent(0, ev_c1, 0);
    gemm_score_f16<<<dim3(NSPLIT, CHUNK_ROWS/BM), 128, dyn_smem>>>(Wo, CHUNK_ROWS);
    softmax_kernel<<<HALF_B, 1024>>>(HALF_B);
    ctx_partial_kernel<<<dim3(HALF_B, CSPLIT), 256>>>(HALF_B);
    cudaStreamWaitEvent(0, ev_t2, 0);
    ctx_reduce_kernel<<<BB*EE/256, 256>>>((float*)d_out);
}

// round 14
// speedup vs baseline: 1.2105x; 1.2105x over previous
#include <cuda_runtime.h>
#include <cuda_fp16.h>
#include <cstdint>

// Problem constants
#define BB 16
#define SS 4096
#define EE 1024
#define HH 512
#define NROWS (BB*SS)          // 65536
#define NSPLIT 8               // H split (BN=64)
#define CSPLIT 32              // s-split for context pass

// GEMM tiling: BM=128 x BN=64, 128 threads (4 warps, warp tile 64x32)
#define BM 128
#define BN 64
#define BK 64                  // fp16 elems = 128B rows (SW128 atom)
#define KITERS (EE/BK)         // 16
#define STAGES 2
#define A_BYTES (BM*BK*2)      // 16384
#define B_BYTES (BN*BK*2)      // 8192
#define STAGE_BYTES (A_BYTES + B_BYTES)  // 24576

// Scratch (__device__ globals; allocation-free rule), 16B+ aligned.
__device__ __align__(128) __half g_encH[(size_t)NROWS*EE];   // fp16 encoder copy
__device__ __align__(128) __half g_WeTh[HH*EE];              // We^T fp16, K-major
__device__ __align__(128) float  g_comb[BB*HH];              // dec_proj + bd + be
__device__ __align__(128) float  g_partial[NSPLIT*NROWS];    // partial scores
__device__ __align__(128) float  g_attn[NROWS];              // softmax weights
__device__ __align__(128) float  g_ctx_part[CSPLIT*BB*EE];   // context partials

__device__ __forceinline__ uint32_t smem_u32(const void* p) {
    uint32_t a;
    asm("{ .reg .u64 t; cvta.to.shared.u64 t, %1; cvt.u32.u64 %0, t; }" : "=r"(a) : "l"(p));
    return a;
}
__device__ __forceinline__ void cp16(uint32_t dst, const void* src) {
    asm volatile("cp.async.cg.shared.global [%0], [%1], 16;" :: "r"(dst), "l"(src) : "memory");
}
__device__ __forceinline__ void ldmatrix_x4(uint32_t r[4], uint32_t addr) {
    asm volatile("ldmatrix.sync.aligned.m8n8.x4.shared.b16 {%0,%1,%2,%3}, [%4];"
                 : "=r"(r[0]), "=r"(r[1]), "=r"(r[2]), "=r"(r[3]) : "r"(addr));
}
__device__ __forceinline__ void mma_f16(float d[4], const uint32_t a[4], const uint32_t b[2]) {
    asm volatile(
        "mma.sync.aligned.m16n8k16.row.col.f32.f16.f16.f32 "
        "{%0,%1,%2,%3}, {%4,%5,%6,%7}, {%8,%9}, {%0,%1,%2,%3};"
        : "+f"(d[0]), "+f"(d[1]), "+f"(d[2]), "+f"(d[3])
        : "r"(a[0]), "r"(a[1]), "r"(a[2]), "r"(a[3]), "r"(b[0]), "r"(b[1]));
}

// ---------------------------------------------------------------------------
// Convert encoder fp32 -> fp16. 32 floats per thread (8 staged float4 loads).
// ---------------------------------------------------------------------------
__global__ __launch_bounds__(256) void convert_enc_kernel(const float4* __restrict__ in) {
    const size_t i = (size_t)blockIdx.x * 256 + threadIdx.x;
    float4 v[8];
    #pragma unroll
    for (int j = 0; j < 8; j++) v[j] = in[i*8 + j];
    #pragma unroll
    for (int j = 0; j < 4; j++) {
        __half2 h0 = __floats2half2_rn(v[2*j].x,   v[2*j].y);
        __half2 h1 = __floats2half2_rn(v[2*j].z,   v[2*j].w);
        __half2 h2 = __floats2half2_rn(v[2*j+1].x, v[2*j+1].y);
        __half2 h3 = __floats2half2_rn(v[2*j+1].z, v[2*j+1].w);
        uint4 o;
        o.x = *reinterpret_cast<uint32_t*>(&h0);
        o.y = *reinterpret_cast<uint32_t*>(&h1);
        o.z = *reinterpret_cast<uint32_t*>(&h2);
        o.w = *reinterpret_cast<uint32_t*>(&h3);
        reinterpret_cast<uint4*>(g_encH)[i*4 + j] = o;
    }
}

// ---------------------------------------------------------------------------
// We [1024,512] -> g_WeTh [512,1024] fp16 (transposed, K-major).
// ---------------------------------------------------------------------------
__global__ __launch_bounds__(256) void convert_we_kernel(const float* __restrict__ We) {
    __shared__ float t[32][33];
    const int bx = blockIdx.x;  // K block (32)
    const int by = blockIdx.y;  // N block (16)
    const int x = threadIdx.x & 31;
    const int y = threadIdx.x >> 5;
    #pragma unroll
    for (int i = 0; i < 32; i += 8)
        t[y + i][x] = We[(bx*32 + y + i)*HH + by*32 + x];
    __syncthreads();
    #pragma unroll
    for (int i = 0; i < 32; i += 8)
        g_WeTh[(by*32 + y + i)*EE + bx*32 + x] = __float2half_rn(t[x][y + i]);
}

// ---------------------------------------------------------------------------
// dec_proj: comb[b,h] = dec[b,:] @ Wd[:,h] + bd[h] + be[h].
// Grid (16, 8): 64 h-lanes x 4 K-quarters; smem combine.
// ---------------------------------------------------------------------------
__global__ __launch_bounds__(256) void dec_proj_kernel(
    const float* __restrict__ dec, const float* __restrict__ Wd,
    const float* __restrict__ be, const float* __restrict__ bd) {
    __shared__ float sd[EE];
    __shared__ float part[4][64];
    const int b = blockIdx.x;
    const int hl = threadIdx.x & 63;
    const int q  = threadIdx.x >> 6;          // 0..3
    const int h  = blockIdx.y * 64 + hl;
    for (int i = threadIdx.x; i < EE; i += 256) sd[i] = dec[b*EE + i];
    __syncthreads();
    const float* wp = Wd + (size_t)(q*256)*HH + h;
    const float* dp = sd + q*256;
    float a0 = 0.f, a1 = 0.f, a2 = 0.f, a3 = 0.f;
    #pragma unroll 4
    for (int k = 0; k < 256; k += 4) {
        a0 += dp[k  ] * wp[(size_t)(k  )*HH];
        a1 += dp[k+1] * wp[(size_t)(k+1)*HH];
        a2 += dp[k+2] * wp[(size_t)(k+2)*HH];
        a3 += dp[k+3] * wp[(size_t)(k+3)*HH];
    }
    part[q][hl] = (a0 + a1) + (a2 + a3);
    __syncthreads();
    if (q == 0)
        g_comb[b*HH + h] = (part[0][hl] + part[1][hl]) + (part[2][hl] + part[3][hl])
                         + bd[h] + be[h];
}

// ---------------------------------------------------------------------------
// fp16 GEMM (mma.m16n8k16) + tanh score epilogue.
// 128 threads = 4 warps (2m x 2n), warp tile 64m x 32n.
// 2-stage cp.async ring + single-buffered fragments -> regs<=128 ->
// 4 CTAs/SM (16 warps). Two barriers per K-iter (consume, then refill slot).
// ---------------------------------------------------------------------------
__global__ __launch_bounds__(128, 4) void gemm_score_f16(const float* __restrict__ Wo) {
    extern __shared__ char dsmem_raw[];
    __shared__ float red[2][BM];
    __shared__ float sm_comb[BN], sm_wo[BN];

    const int tid = threadIdx.x;
    const int n0  = blockIdx.x * BN;
    const int r0  = blockIdx.y * BM;
    const int b   = r0 >> 12;

    const uint32_t smem_base = (smem_u32(dsmem_raw) + 127u) & ~127u;

    if (tid < BN) {
        sm_comb[tid] = g_comb[b*HH + n0 + tid];
        sm_wo[tid]   = Wo[n0 + tid];
    }

    const int warp = tid >> 5;
    const int lane = tid & 31;
    const int wm = warp >> 1;       // m-warp: rows wm*64..+63
    const int wn = warp & 1;        // n-warp: cols wn*32..+31
    const int g  = lane >> 2;
    const int tig = lane & 3;

    const __half* gA = g_encH + (size_t)r0 * EE;
    const __half* gB = g_WeTh + (size_t)n0 * EE;

    const int lrow = tid >> 3;          // 0..15
    const int lcb  = (tid & 7) * 16;
    const uint32_t st_sw = (uint32_t)(lrow*128 + lcb) ^ ((lrow & 7) << 4);

    float acc[4][4][4];
    #pragma unroll
    for (int mb = 0; mb < 4; mb++)
        #pragma unroll
        for (int nb = 0; nb < 4; nb++)
            #pragma unroll
            for (int e = 0; e < 4; e++) acc[mb][nb][e] = 0.f;

    uint32_t a_raw[4], a_xor[4];
    #pragma unroll
    for (int mb = 0; mb < 4; mb++) {
        int row = wm*64 + mb*16 + (lane & 15);
        a_raw[mb] = row*128 + ((lane >> 4) * 16);
        a_xor[mb] = (row & 7) << 4;
    }
    uint32_t b_raw[2], b_xor[2];
    #pragma unroll
    for (int p = 0; p < 2; p++) {
        int row = wn*32 + p*16 + ((lane & 16) ? 8 : 0) + (lane & 7);
        b_raw[p] = row*128 + (((lane >> 3) & 1) * 16);
        b_xor[p] = (row & 7) << 4;
    }

    // prologue: fill stages 0,1 (iters 0,1), one commit group each
    #pragma unroll
    for (int p = 0; p < STAGES; p++) {
        uint32_t stA = smem_base + p*STAGE_BYTES;
        uint32_t stB = stA + A_BYTES;
        const int k0 = p * BK;
        #pragma unroll
        for (int u = 0; u < 8; u++)
            cp16(stA + st_sw + u*2048, (const char*)(gA + (size_t)(lrow + u*16)*EE + k0) + lcb);
        #pragma unroll
        for (int u = 0; u < 4; u++)
            cp16(stB + st_sw + u*2048, (const char*)(gB + (size_t)(lrow + u*16)*EE + k0) + lcb);
        asm volatile("cp.async.commit_group;" ::: "memory");
    }

    for (int i = 0; i < KITERS; i++) {
        // pending: {L(i), L(i+1)} -> wait until only 1 pending => L(i) done
        asm volatile("cp.async.wait_group 1;" ::: "memory");
        __syncthreads();

        const uint32_t stA = smem_base + (i & 1)*STAGE_BYTES;
        const uint32_t stB = stA + A_BYTES;

        // compute: single-buffered fragments per k-step
        #pragma unroll
        for (int ks = 0; ks < 4; ks++) {
            uint32_t afr[4][4], bfr[4][2];
            #pragma unroll
            for (int mb = 0; mb < 4; mb++)
                ldmatrix_x4(afr[mb], stA + ((a_raw[mb] + ks*32) ^ a_xor[mb]));
            #pragma unroll
            for (int p = 0; p < 2; p++) {
                uint32_t r[4];
                ldmatrix_x4(r, stB + ((b_raw[p] + ks*32) ^ b_xor[p]));
                bfr[2*p][0]   = r[0]; bfr[2*p][1]   = r[1];
                bfr[2*p+1][0] = r[2]; bfr[2*p+1][1] = r[3];
            }
            #pragma unroll
            for (int mb = 0; mb < 4; mb++)
                #pragma unroll
                for (int nb = 0; nb < 4; nb++)
                    mma_f16(acc[mb][nb], afr[mb], bfr[nb]);
        }

        // all warps done with slot i&1 -> safe to refill with L(i+2)
        __syncthreads();
        if (i + 2 < KITERS) {
            uint32_t nA = smem_base + (i & 1)*STAGE_BYTES;
            uint32_t nB = nA + A_BYTES;
            const int k0 = (i + 2) * BK;
            #pragma unroll
            for (int u = 0; u < 8; u++)
                cp16(nA + st_sw + u*2048, (const char*)(gA + (size_t)(lrow + u*16)*EE + k0) + lcb);
            #pragma unroll
            for (int u = 0; u < 4; u++)
                cp16(nB + st_sw + u*2048, (const char*)(gB + (size_t)(lrow + u*16)*EE + k0) + lcb);
        }
        asm volatile("cp.async.commit_group;" ::: "memory");  // group i+2 (may be empty)
    }

    // Epilogue: score = sum_n tanh(acc + comb[n]) * wo[n]  (bo shift-invariant)
    float rs[4][2];
    #pragma unroll
    for (int mb = 0; mb < 4; mb++) { rs[mb][0] = 0.f; rs[mb][1] = 0.f; }
    #pragma unroll
    for (int mb = 0; mb < 4; mb++) {
        #pragma unroll
        for (int nb = 0; nb < 4; nb++) {
            int col = wn*32 + nb*8 + tig*2;
            float c0 = sm_comb[col], c1 = sm_comb[col+1];
            float w0 = sm_wo[col],   w1 = sm_wo[col+1];
            float t0, t1, t2, t3;
            asm("tanh.approx.f32 %0, %1;" : "=f"(t0) : "f"(acc[mb][nb][0] + c0));
            asm("tanh.approx.f32 %0, %1;" : "=f"(t1) : "f"(acc[mb][nb][1] + c1));
            asm("tanh.approx.f32 %0, %1;" : "=f"(t2) : "f"(acc[mb][nb][2] + c0));
            asm("tanh.approx.f32 %0, %1;" : "=f"(t3) : "f"(acc[mb][nb][3] + c1));
            rs[mb][0] += t0*w0 + t1*w1;
            rs[mb][1] += t2*w0 + t3*w1;
        }
    }
    #pragma unroll
    for (int mb = 0; mb < 4; mb++)
        #pragma unroll
        for (int hh = 0; hh < 2; hh++) {
            float v = rs[mb][hh];
            v += __shfl_xor_sync(0xffffffffu, v, 1);
            v += __shfl_xor_sync(0xffffffffu, v, 2);
            if (tig == 0) red[wn][wm*64 + mb*16 + hh*8 + g] = v;
        }
    __syncthreads();
    if (tid < BM)
        g_partial[blockIdx.x * NROWS + r0 + tid] = red[0][tid] + red[1][tid];
}

// ---------------------------------------------------------------------------
// softmax over S per batch (sums 8 N-chunk partials)
// ---------------------------------------------------------------------------
__global__ __launch_bounds__(1024) void softmax_kernel() {
    const int b = blockIdx.x;
    const int tid = threadIdx.x;
    __shared__ float sred[32];
    __shared__ float sbcast;

    float sc[4];
    float m = -1e30f;
    #pragma unroll
    for (int i = 0; i < 4; i++) {
        int s = b*SS + tid + i*1024;
        float v = 0.f;
        #pragma unroll
        for (int p = 0; p < NSPLIT; p++) v += g_partial[p*NROWS + s];
        sc[i] = v;
        m = fmaxf(m, v);
    }
    #pragma unroll
    for (int o = 16; o; o >>= 1) m = fmaxf(m, __shfl_xor_sync(0xffffffffu, m, o));
    if ((tid & 31) == 0) sred[tid >> 5] = m;
    __syncthreads();
    if (tid < 32) {
        float v = sred[tid];
        #pragma unroll
        for (int o = 16; o; o >>= 1) v = fmaxf(v, __shfl_xor_sync(0xffffffffu, v, o));
        if (tid == 0) sbcast = v;
    }
    __syncthreads();
    const float bm = sbcast;

    float sum = 0.f;
    #pragma unroll
    for (int i = 0; i < 4; i++) { sc[i] = __expf(sc[i] - bm); sum += sc[i]; }
    #pragma unroll
    for (int o = 16; o; o >>= 1) sum += __shfl_xor_sync(0xffffffffu, sum, o);
    __syncthreads();
    if ((tid & 31) == 0) sred[tid >> 5] = sum;
    __syncthreads();
    if (tid < 32) {
        float v = sred[tid];
        #pragma unroll
        for (int o = 16; o; o >>= 1) v += __shfl_xor_sync(0xffffffffu, v, o);
        if (tid == 0) sbcast = v;
    }
    __syncthreads();
    const float inv = 1.0f / sbcast;
    #pragma unroll
    for (int i = 0; i < 4; i++) g_attn[b*SS + tid + i*1024] = sc[i] * inv;
}

// ---------------------------------------------------------------------------
// Context partials from fp16 encoder copy. Grid (16, 32), block 256.
// ---------------------------------------------------------------------------
__global__ __launch_bounds__(256) void ctx_partial_kernel() {
    __shared__ float sa[128];
    __shared__ float part[128][8];
    const int b = blockIdx.x, sp = blockIdx.y;
    const int tid = threadIdx.x;
    const int half = tid >> 7;
    const int c = tid & 127;
    if (tid < 128) sa[tid] = g_attn[b*SS + sp*128 + tid];
    __syncthreads();

    const __half* ep = g_encH + ((size_t)(b*SS + sp*128 + half)) * EE + c*8;
    float a[8] = {0,0,0,0,0,0,0,0};
    #pragma unroll 8
    for (int s = 0; s < 128; s += 2) {
        uint4 v = *reinterpret_cast<const uint4*>(ep + (size_t)s*EE);
        float w = sa[s + half];
        __half2 h0 = *reinterpret_cast<__half2*>(&v.x);
        __half2 h1 = *reinterpret_cast<__half2*>(&v.y);
        __half2 h2 = *reinterpret_cast<__half2*>(&v.z);
        __half2 h3 = *reinterpret_cast<__half2*>(&v.w);
        float2 f0 = __half22float2(h0), f1 = __half22float2(h1);
        float2 f2 = __half22float2(h2), f3 = __half22float2(h3);
        a[0] += w*f0.x; a[1] += w*f0.y; a[2] += w*f1.x; a[3] += w*f1.y;
        a[4] += w*f2.x; a[5] += w*f2.y; a[6] += w*f3.x; a[7] += w*f3.y;
    }
    if (half == 1) {
        #pragma unroll
        for (int j = 0; j < 8; j++) part[c][j] = a[j];
    }
    __syncthreads();
    if (half == 0) {
        float4 o0, o1;
        o0.x = a[0] + part[c][0]; o0.y = a[1] + part[c][1];
        o0.z = a[2] + part[c][2]; o0.w = a[3] + part[c][3];
        o1.x = a[4] + part[c][4]; o1.y = a[5] + part[c][5];
        o1.z = a[6] + part[c][6]; o1.w = a[7] + part[c][7];
        float* dst = &g_ctx_part[(size_t)(sp*BB + b)*EE + c*8];
        *reinterpret_cast<float4*>(dst)     = o0;
        *reinterpret_cast<float4*>(dst + 4) = o1;
    }
}

// ---------------------------------------------------------------------------
// Final reduce of context partials.
// ---------------------------------------------------------------------------
__global__ __launch_bounds__(256) void ctx_reduce_kernel(float* __restrict__ out) {
    const int i = blockIdx.x * 256 + threadIdx.x;  // 16384 outputs
    float acc = 0.f;
    #pragma unroll
    for (int s = 0; s < CSPLIT; s++) acc += g_ctx_part[(size_t)s*BB*EE + i];
    out[i] = acc;
}

// ---------------------------------------------------------------------------
extern "C" void kernel_launch(void* const* d_in, const int* in_sizes, int n_in,
                              void* d_out, int out_size) {
    const float* enc = (const float*)d_in[0];  // [16,4096,1024]
    const float* dec = (const float*)d_in[1];  // [16,1024]
    const float* We  = (const float*)d_in[2];  // [1024,512]
    const float* be  = (const float*)d_in[3];  // [512]
    const float* Wd  = (const float*)d_in[4];  // [1024,512]
    const float* bd  = (const float*)d_in[5];  // [512]
    const float* Wo  = (const float*)d_in[6];  // [512,1]
    // d_in[7] = bo: softmax shift-invariant -> unused.

    // One-time side stream + events (resource init; captured graph identical
    // every capture).
    static cudaStream_t s2 = nullptr;
    static cudaEvent_t ev_fork = nullptr, ev_join = nullptr;
    if (s2 == nullptr) {
        cudaStreamCreateWithFlags(&s2, cudaStreamNonBlocking);
        cudaEventCreateWithFlags(&ev_fork, cudaEventDisableTiming);
        cudaEventCreateWithFlags(&ev_join, cudaEventDisableTiming);
    }

    const int dyn_smem = STAGES*STAGE_BYTES + 256;  // 49408
    cudaFuncSetAttribute(gemm_score_f16,
                         cudaFuncAttributeMaxDynamicSharedMemorySize, dyn_smem);

    // Fork: small weight-side kernels on s2, overlapping convert_enc.
    cudaEventRecord(ev_fork, 0);
    cudaStreamWaitEvent(s2, ev_fork, 0);
    convert_we_kernel<<<dim3(EE/32, HH/32), 256, 0, s2>>>(We);
    dec_proj_kernel<<<dim3(BB, HH/64), 256, 0, s2>>>(dec, Wd, be, bd);
    cudaEventRecord(ev_join, s2);

    // Main chain on the default stream.
    convert_enc_kernel<<<(NROWS*(EE/32))/256, 256>>>((const float4*)enc);
    cudaStreamWaitEvent(0, ev_join, 0);
    gemm_score_f16<<<dim3(NSPLIT, NROWS/BM), 128, dyn_smem>>>(Wo);
    softmax_kernel<<<BB, 1024>>>();
    ctx_partial_kernel<<<dim3(BB, CSPLIT), 256>>>();
    ctx_reduce_kernel<<<BB*EE/256, 256>>>((float*)d_out);
}